// round 17
// baseline (speedup 1.0000x reference)
#include <cuda_runtime.h>
#include <cuda_fp16.h>
#include <cstdint>

#define S_LEN 2048
#define DMODEL 1024
#define NHEADS 16
#define DK 64
#define BATCH 4
#define MTOT (BATCH * S_LEN)   // 8192
#define MQTR (MTOT / 4)        // 2048 rows = one batch

typedef __half f16;

// ---------------- scratch (__device__ globals; no allocs allowed) -------------
__device__ f16 g_xh[(size_t)MTOT * DMODEL];
__device__ f16 g_Qh[(size_t)MTOT * DMODEL];
__device__ f16 g_Kh[(size_t)MTOT * DMODEL];
__device__ f16 g_Vh[(size_t)MTOT * DMODEL];
__device__ f16 g_Oh[(size_t)MTOT * DMODEL];
__device__ f16 g_wq[(size_t)DMODEL * DMODEL];
__device__ f16 g_wk[(size_t)DMODEL * DMODEL];
__device__ f16 g_wv[(size_t)DMODEL * DMODEL];
__device__ f16 g_wo[(size_t)DMODEL * DMODEL];
__device__ float2 g_rope[S_LEN * 32];     // [pos][ipair] -> (cos, sin)

// ---------------- helpers -----------------------------------------------------
__device__ __forceinline__ uint32_t smem_u32(const void* p) {
    uint32_t a;
    asm("{ .reg .u64 t; cvta.to.shared.u64 t, %1; cvt.u32.u64 %0, t; }" : "=r"(a) : "l"(p));
    return a;
}
__device__ __forceinline__ void cp16(uint32_t dst, const void* src) {
    asm volatile("cp.async.cg.shared.global [%0], [%1], 16;" :: "r"(dst), "l"(src) : "memory");
}
// L1-caching variant: W tiles are shared by the co-resident CTA pair on each SM
__device__ __forceinline__ void cp16ca(uint32_t dst, const void* src) {
    asm volatile("cp.async.ca.shared.global [%0], [%1], 16;" :: "r"(dst), "l"(src) : "memory");
}
__device__ __forceinline__ void ldmx4(uint32_t* r, uint32_t addr) {
    asm volatile("ldmatrix.sync.aligned.m8n8.x4.shared.b16 {%0,%1,%2,%3}, [%4];"
        : "=r"(r[0]), "=r"(r[1]), "=r"(r[2]), "=r"(r[3]) : "r"(addr));
}
__device__ __forceinline__ void ldmx4t(uint32_t* r, uint32_t addr) {
    asm volatile("ldmatrix.sync.aligned.m8n8.x4.trans.shared.b16 {%0,%1,%2,%3}, [%4];"
        : "=r"(r[0]), "=r"(r[1]), "=r"(r[2]), "=r"(r[3]) : "r"(addr));
}
__device__ __forceinline__ void mma_f16(float* d, const uint32_t* a, const uint32_t* b) {
    asm volatile("mma.sync.aligned.m16n8k16.row.col.f32.f16.f16.f32 "
        "{%0,%1,%2,%3}, {%4,%5,%6,%7}, {%8,%9}, {%0,%1,%2,%3};"
        : "+f"(d[0]), "+f"(d[1]), "+f"(d[2]), "+f"(d[3])
        : "r"(a[0]), "r"(a[1]), "r"(a[2]), "r"(a[3]), "r"(b[0]), "r"(b[1]));
}
__device__ __forceinline__ uint32_t pack2(float a, float b) {
    __half2 h = __floats2half2_rn(a, b);
    return *(uint32_t*)&h;
}
__device__ __forceinline__ float ex2f(float x) {
    float y; asm("ex2.approx.f32 %0, %1;" : "=f"(y) : "f"(x)); return y;
}
__device__ __forceinline__ uint32_t ex2h2(uint32_t a) {
    uint32_t d; asm("ex2.approx.f16x2 %0, %1;" : "=r"(d) : "r"(a)); return d;
}
__device__ __forceinline__ uint32_t hadd2u(uint32_t a, uint32_t b) {
    __half2 r = __hadd2(*(__half2*)&a, *(__half2*)&b);
    return *(uint32_t*)&r;
}

#define WINV (1.0f / 512.0f)
#define ATTSC 0.1803368801111204f   // 1/sqrt(64) * log2(e), folded into Q

// ------- fused fp32->fp16 split + RoPE table build (one launch) ---------------
__global__ __launch_bounds__(256) void split_all(
    const float* __restrict__ x,  const float* __restrict__ pq,
    const float* __restrict__ pk, const float* __restrict__ pv,
    const float* __restrict__ po,
    f16* __restrict__ xh, f16* __restrict__ wq, f16* __restrict__ wk,
    f16* __restrict__ wv, f16* __restrict__ wo)
{
    const int NX = MTOT * DMODEL / 4;
    const int NW = DMODEL * DMODEL / 4;
    const int NR = S_LEN * 32;          // rope entries
    const int total = NX + 4 * NW + NR;
    int i = blockIdx.x * blockDim.x + threadIdx.x;
    for (; i < total; i += gridDim.x * blockDim.x) {
        if (i >= NX + 4 * NW) {
            const float L2T = 13.287712379549449f / 32.0f;
            int e = i - (NX + 4 * NW);
            int pos = e >> 5, ip = e & 31;
            float sn, cs;
            sincosf((float)pos * exp2f(-(float)ip * L2T), &sn, &cs);
            g_rope[e] = make_float2(cs, sn);
            continue;
        }
        const float* src; f16* dst; int j; float sc;
        if (i < NX) { src = x; dst = xh; j = i; sc = 1.0f; }
        else {
            int t = i - NX; int s = t / NW; j = t - s * NW; sc = 512.0f;
            src = (s == 0) ? pq : (s == 1) ? pk : (s == 2) ? pv : po;
            dst = (s == 0) ? wq : (s == 1) ? wk : (s == 2) ? wv : wo;
        }
        float4 v = ((const float4*)src)[j];
        ((uint32_t*)dst)[2*j]   = pack2(v.x * sc, v.y * sc);
        ((uint32_t*)dst)[2*j+1] = pack2(v.z * sc, v.w * sc);
    }
}

// ---------------- HMMA fp16 GEMM (1-term): C[m,n] = sum_k A[m,k] W[n,k] -------
#define CHUNK 64
#define TILE_B 16384                 // 128 x 64 fp16
#define STAGE_B (2 * TILE_B)         // A + W
#define GEMM_SMEM (3 * STAGE_B)      // 96 KB

// ca=0: L2-only (.cg, private A stream); ca=1: L1-cached (.ca, shared W stream)
__device__ __forceinline__ void stage_load(uint32_t sbase, const f16* __restrict__ g,
                                           int tid, int ca)
{
#pragma unroll
    for (int i = 0; i < 4; ++i) {
        int e = i * 256 + tid;
        int r = e >> 3, u = e & 7;
        uint32_t dst = sbase + r * 128 + ((u ^ (r & 7)) << 4);
        const void* src = g + (size_t)r * DMODEL + u * 8;
        if (ca) cp16ca(dst, src);
        else    cp16(dst, src);
    }
}

__device__ __forceinline__ void gemm_body(
    const f16* __restrict__ A, const f16* __restrict__ W,
    float* __restrict__ C, f16* __restrict__ Ch, int mode, float esc,
    int m0, int n0, char* smem)
{
    const uint32_t sb = smem_u32(smem);
    const int tid = threadIdx.x;
    const int w = tid >> 5, l = tid & 31;
    const int mw = w & 3, nw = w >> 2;

    const f16* gA = A + (size_t)m0 * DMODEL;
    const f16* gW = W + (size_t)n0 * DMODEL;

    auto issue = [&](int c) {
        uint32_t st = sb + (uint32_t)(c % 3) * STAGE_B;
        int kb = c * CHUNK;
        stage_load(st,          gA + kb, tid, 0);   // A: private -> .cg
        stage_load(st + TILE_B, gW + kb, tid, 1);   // W: shared by CTA pair -> .ca
        asm volatile("cp.async.commit_group;" ::: "memory");
    };

    issue(0); issue(1); issue(2);

    float acc[2][8][4] = {};

    const int rA  = (l & 15);
    const int kA8 = (l >> 4);
    const int rB  = ((l >> 4) << 3) + (l & 7);
    const int kB8 = ((l >> 3) & 1);

    for (int c = 0; c < 16; ++c) {
        asm volatile("cp.async.wait_group 2;" ::: "memory");
        __syncthreads();
        const uint32_t st = sb + (uint32_t)(c % 3) * STAGE_B;

#pragma unroll
        for (int ks = 0; ks < 4; ++ks) {
            uint32_t ah[2][4];
#pragma unroll
            for (int mt = 0; mt < 2; ++mt) {
                int row = mw * 32 + mt * 16 + rA;
                uint32_t off = row * 128 + (((2*ks + kA8) ^ (row & 7)) << 4);
                ldmx4(ah[mt], st + off);
            }
#pragma unroll
            for (int nt = 0; nt < 4; ++nt) {
                int row = nw * 64 + nt * 16 + rB;
                uint32_t off = row * 128 + (((2*ks + kB8) ^ (row & 7)) << 4);
                uint32_t bh[4];
                ldmx4(bh, st + TILE_B + off);
#pragma unroll
                for (int mt = 0; mt < 2; ++mt)
#pragma unroll
                    for (int h = 0; h < 2; ++h)
                        mma_f16(acc[mt][nt*2 + h], ah[mt], &bh[2*h]);
            }
        }
        __syncthreads();
        if (c + 3 < 16) issue(c + 3);
        else asm volatile("cp.async.commit_group;" ::: "memory");
    }

#pragma unroll
    for (int mt = 0; mt < 2; ++mt) {
        const int rbase = m0 + mw * 32 + mt * 16 + (l >> 2);
#pragma unroll
        for (int half = 0; half < 2; ++half) {
            const int r = rbase + half * 8;
            const int posb = (r & (S_LEN - 1)) << 5;
#pragma unroll
            for (int j = 0; j < 8; ++j) {
                const int cc = n0 + nw * 64 + j * 8 + 2 * (l & 3);
                float x1 = acc[mt][j][half*2] * esc, x2 = acc[mt][j][half*2 + 1] * esc;
                if (mode == 0) {
                    *(float2*)(C + (size_t)r * DMODEL + cc) = make_float2(x1, x2);
                } else if (mode == 1) {
                    const float2 t = g_rope[posb + ((cc & (DK - 1)) >> 1)];
                    *(uint32_t*)(Ch + (size_t)r * DMODEL + cc) =
                        pack2(x1 * t.x - x2 * t.y, x1 * t.y + x2 * t.x);
                } else {
                    *(uint32_t*)(Ch + (size_t)r * DMODEL + cc) = pack2(x1, x2);
                }
            }
        }
    }
}

// merged Q/K/V projection over a row range: gridDim.z picks weight/mode/dst
__global__ __launch_bounds__(256, 2) void gemm_qkv_kernel(
    const f16* __restrict__ A,
    const f16* __restrict__ Wq, const f16* __restrict__ Wk, const f16* __restrict__ Wv,
    f16* __restrict__ Qh, f16* __restrict__ Kh, f16* __restrict__ Vh, int moff)
{
    extern __shared__ char smem[];
    const int z = blockIdx.z;
    const f16* W = (z == 0) ? Wq : (z == 1) ? Wk : Wv;
    f16* Ch      = (z == 0) ? Qh : (z == 1) ? Kh : Vh;
    const float esc = (z == 0) ? WINV * ATTSC : WINV;
    gemm_body(A, W, nullptr, Ch, (z == 2) ? 2 : 1, esc,
              moff + blockIdx.x * 128, blockIdx.y * 128, smem);
}

// out-projection (fp32 output) over a row range
__global__ __launch_bounds__(256, 2) void gemm_out_kernel(
    const f16* __restrict__ A, const f16* __restrict__ W, float* __restrict__ C, int moff)
{
    extern __shared__ char smem[];
    gemm_body(A, W, C, nullptr, 0, WINV, moff + blockIdx.x * 128, blockIdx.y * 128, smem);
}

// ---------------- HMMA flash attention (fp16, causal) -------------------------
// 64 q-rows / 128 threads / 4 warps per CTA; 4 CTAs/SM (exact RF + smem fit).
// smem: Q 8K; stages at 8192 + (kt%3)*16K (K 0, V 8K within stage).
#define AST_B 16384
#define ATT_SMEM (8192 + 3 * AST_B)    // 56 KB

__global__ __launch_bounds__(128, 4) void attn_f16_kernel(
    const f16* __restrict__ Qh, const f16* __restrict__ Kh,
    const f16* __restrict__ Vh, f16* __restrict__ Oh, int boff)
{
    extern __shared__ char smem[];
    const uint32_t sb = smem_u32(smem);
    const int tid = threadIdx.x, w = tid >> 5, l = tid & 31;
    const int qtile = gridDim.x - 1 - blockIdx.x;   // long tiles first
    const int h = blockIdx.y, b = blockIdx.z + boff;
    const int qb = qtile * 64;
    const int nkt = qtile + 1;
    const size_t rowbase = (size_t)b * S_LEN;

    const f16* gQ = Qh + (rowbase + qb) * DMODEL + h * DK;
    const f16* gK = Kh + rowbase * DMODEL + h * DK;
    const f16* gV = Vh + rowbase * DMODEL + h * DK;

    auto issue_kv = [&](int kt) {
        if (kt < nkt) {
            uint32_t st = sb + 8192 + (uint32_t)(kt % 3) * AST_B;
            const size_t kof = (size_t)(kt * 64) * DMODEL;
#pragma unroll
            for (int i = 0; i < 4; ++i) {
                int e = i * 128 + tid;          // 0..511
                int r = e >> 3, u = e & 7;
                uint32_t off = r * 128 + ((u ^ (r & 7)) << 4);
                size_t g = kof + (size_t)r * DMODEL + u * 8;
                cp16(st + off,        gK + g);
                cp16(st + 8192 + off, gV + g);
            }
        }
        asm volatile("cp.async.commit_group;" ::: "memory");
    };

    // group 0: Q (64 rows) + KV tile 0
#pragma unroll
    for (int i = 0; i < 4; ++i) {
        int e = i * 128 + tid;                  // 0..511
        int r = e >> 3, u = e & 7;
        uint32_t off = r * 128 + ((u ^ (r & 7)) << 4);
        cp16(sb + off, gQ + (size_t)r * DMODEL + u * 8);
    }
    {
        uint32_t st = sb + 8192;
#pragma unroll
        for (int i = 0; i < 4; ++i) {
            int e = i * 128 + tid;
            int r = e >> 3, u = e & 7;
            uint32_t off = r * 128 + ((u ^ (r & 7)) << 4);
            size_t g = (size_t)r * DMODEL + u * 8;
            cp16(st + off,        gK + g);
            cp16(st + 8192 + off, gV + g);
        }
        asm volatile("cp.async.commit_group;" ::: "memory");
    }
    issue_kv(1);
    issue_kv(2);

    asm volatile("cp.async.wait_group 2;" ::: "memory");
    __syncthreads();

    uint32_t qf[4][4];
    {
        const int rA = l & 15, kA8 = l >> 4;
        const int row = w * 16 + rA;
#pragma unroll
        for (int kd = 0; kd < 4; ++kd) {
            uint32_t off = row * 128 + (((2*kd + kA8) ^ (row & 7)) << 4);
            ldmx4(qf[kd], sb + off);
        }
    }

    float o[8][4] = {};
    float m_[2] = {-1e30f, -1e30f}, l_[2] = {0.f, 0.f};
    const int row0 = qb + w * 16 + (l >> 2);

    for (int kt = 0; kt < nkt; ++kt) {
        if (kt > 0) {
            asm volatile("cp.async.wait_group 2;" ::: "memory");
            __syncthreads();
        }
        const uint32_t st = sb + 8192 + (uint32_t)(kt % 3) * AST_B;

        // S = Q K^T  (scores in log2-softmax units via Q prescale)
        float s[8][4] = {};
#pragma unroll
        for (int kd = 0; kd < 4; ++kd) {
#pragma unroll
            for (int ntp = 0; ntp < 4; ++ntp) {
                const int rB = ntp * 16 + ((l >> 4) << 3) + (l & 7);
                uint32_t off = rB * 128 + (((2*kd + ((l >> 3) & 1)) ^ (rB & 7)) << 4);
                uint32_t bh[4];
                ldmx4(bh, st + off);
#pragma unroll
                for (int hh = 0; hh < 2; ++hh)
                    mma_f16(s[ntp*2 + hh], qf[kd], &bh[2*hh]);
            }
        }

        // causal mask only on the single diagonal tile
        if (kt == nkt - 1) {
#pragma unroll
            for (int j = 0; j < 8; ++j)
#pragma unroll
                for (int c = 0; c < 4; ++c) {
                    const int col = kt * 64 + 8 * j + 2 * (l & 3) + (c & 1);
                    const int row = row0 + ((c >> 1) << 3);
                    if (col > row) s[j][c] = -1e30f;
                }
        }

        // online softmax (base-2); p as f16x2 pairs = PV A-fragments
        uint32_t ph[8][2];
#pragma unroll
        for (int half = 0; half < 2; ++half) {
            float mx = -1e30f;
#pragma unroll
            for (int j = 0; j < 8; ++j)
                mx = fmaxf(mx, fmaxf(s[j][half*2], s[j][half*2+1]));
            mx = fmaxf(mx, __shfl_xor_sync(0xffffffffu, mx, 1));
            mx = fmaxf(mx, __shfl_xor_sync(0xffffffffu, mx, 2));
            if (__any_sync(0xffffffffu, mx > m_[half])) {
                const float mn = fmaxf(m_[half], mx);
                const float alpha = ex2f(m_[half] - mn);
                l_[half] *= alpha;
                m_[half] = mn;
#pragma unroll
                for (int j = 0; j < 8; ++j) {
                    o[j][half*2]   *= alpha;
                    o[j][half*2+1] *= alpha;
                }
            }
#pragma unroll
            for (int j = 0; j < 8; ++j)
                ph[j][half] = ex2h2(pack2(s[j][half*2]   - m_[half],
                                          s[j][half*2+1] - m_[half]));
            uint32_t t01 = hadd2u(ph[0][half], ph[1][half]);
            uint32_t t23 = hadd2u(ph[2][half], ph[3][half]);
            uint32_t t45 = hadd2u(ph[4][half], ph[5][half]);
            uint32_t t67 = hadd2u(ph[6][half], ph[7][half]);
            uint32_t tt  = hadd2u(hadd2u(t01, t23), hadd2u(t45, t67));
            float2 f = __half22float2(*(__half2*)&tt);
            float rs = f.x + f.y;
            rs += __shfl_xor_sync(0xffffffffu, rs, 1);
            rs += __shfl_xor_sync(0xffffffffu, rs, 2);
            l_[half] += rs;
        }

        // O += P V
#pragma unroll
        for (int kt2 = 0; kt2 < 4; ++kt2) {
            uint32_t pa[4];
            pa[0] = ph[2*kt2][0];
            pa[1] = ph[2*kt2][1];
            pa[2] = ph[2*kt2+1][0];
            pa[3] = ph[2*kt2+1][1];
#pragma unroll
            for (int ntp = 0; ntp < 4; ++ntp) {
                const int rV = kt2 * 16 + (l & 15);
                uint32_t off = rV * 128 + (((2*ntp + (l >> 4)) ^ (rV & 7)) << 4);
                uint32_t vh[4];
                ldmx4t(vh, st + 8192 + off);
#pragma unroll
                for (int hh = 0; hh < 2; ++hh)
                    mma_f16(o[ntp*2 + hh], pa, &vh[2*hh]);
            }
        }
        __syncthreads();
        issue_kv(kt + 3);
    }

#pragma unroll
    for (int half = 0; half < 2; ++half) {
        const float inv = 1.f / l_[half];
        const int row = row0 + half * 8;
        const size_t gr = (rowbase + row) * DMODEL + h * DK;
#pragma unroll
        for (int j = 0; j < 8; ++j) {
            const int cc = 8 * j + 2 * (l & 3);
            *(uint32_t*)(Oh + gr + cc) = pack2(o[j][half*2] * inv, o[j][half*2+1] * inv);
        }
    }
}

// ---------------- launch: four per-batch chains (R13/R15 topology) -------------
// Streams/events created ONCE on the first (uncaptured correctness) call.
static cudaStream_t g_sB[3];
static cudaEvent_t  g_evSplit, g_evDone[3];
static bool         g_init = false;

extern "C" void kernel_launch(void* const* d_in, const int* in_sizes, int n_in,
                              void* d_out, int out_size)
{
    const float* x   = (const float*)d_in[0];
    const float* P_Q = (const float*)d_in[1];
    const float* P_K = (const float*)d_in[2];
    const float* P_V = (const float*)d_in[3];
    const float* P_O = (const float*)d_in[4];
    float* out = (float*)d_out;

    f16 *xh, *qh, *kh, *vh, *oh, *wq, *wk, *wv, *wo;
    cudaGetSymbolAddress((void**)&xh, g_xh);
    cudaGetSymbolAddress((void**)&qh, g_Qh);
    cudaGetSymbolAddress((void**)&kh, g_Kh);
    cudaGetSymbolAddress((void**)&vh, g_Vh);
    cudaGetSymbolAddress((void**)&oh, g_Oh);
    cudaGetSymbolAddress((void**)&wq, g_wq);
    cudaGetSymbolAddress((void**)&wk, g_wk);
    cudaGetSymbolAddress((void**)&wv, g_wv);
    cudaGetSymbolAddress((void**)&wo, g_wo);

    if (!g_init) {
        for (int i = 0; i < 3; ++i) {
            cudaStreamCreateWithFlags(&g_sB[i], cudaStreamNonBlocking);
            cudaEventCreateWithFlags(&g_evDone[i], cudaEventDisableTiming);
        }
        cudaEventCreateWithFlags(&g_evSplit, cudaEventDisableTiming);
        cudaFuncSetAttribute(gemm_qkv_kernel, cudaFuncAttributeMaxDynamicSharedMemorySize, GEMM_SMEM);
        cudaFuncSetAttribute(gemm_out_kernel, cudaFuncAttributeMaxDynamicSharedMemorySize, GEMM_SMEM);
        cudaFuncSetAttribute(attn_f16_kernel, cudaFuncAttributeMaxDynamicSharedMemorySize, ATT_SMEM);
        g_init = true;
    }

    // shared prologue (split + rope) on the main (captured) stream
    split_all<<<4096, 256>>>(x, P_Q, P_K, P_V, P_O, xh, wq, wk, wv, wo);
    cudaEventRecord(g_evSplit, 0);

    dim3 gq(MQTR / 128, DMODEL / 128, 3);   // 16 x 8 x 3
    dim3 ag(S_LEN / 64, NHEADS, 1);         // 32 x 16
    dim3 gg(MQTR / 128, DMODEL / 128);      // 16 x 8

    // chain 0 on the main stream
    gemm_qkv_kernel<<<gq, 256, GEMM_SMEM>>>(xh, wq, wk, wv, qh, kh, vh, 0);
    attn_f16_kernel<<<ag, 128, ATT_SMEM>>>(qh, kh, vh, oh, 0);
    gemm_out_kernel<<<gg, 256, GEMM_SMEM>>>(oh, wo, out, 0);

    // chains 1..3 on side streams
    for (int c = 1; c < 4; ++c) {
        cudaStream_t st = g_sB[c - 1];
        cudaStreamWaitEvent(st, g_evSplit, 0);
        gemm_qkv_kernel<<<gq, 256, GEMM_SMEM, st>>>(xh, wq, wk, wv, qh, kh, vh, c * MQTR);
        attn_f16_kernel<<<ag, 128, ATT_SMEM, st>>>(qh, kh, vh, oh, c);
        gemm_out_kernel<<<gg, 256, GEMM_SMEM, st>>>(oh, wo, out, c * MQTR);
        cudaEventRecord(g_evDone[c - 1], st);
    }

    // join side chains back into the captured origin stream
    for (int i = 0; i < 3; ++i)
        cudaStreamWaitEvent(0, g_evDone[i], 0);
}